// round 8
// baseline (speedup 1.0000x reference)
#include <cuda_runtime.h>

#define N_NODES 100000
#define N_EDGES 1600000
#define IN_DIM  512
#define HID     32
#define BN_EPS  1e-5f

// ---------------- scratch (static device globals; no allocation) ----------------
__device__ float g_h1[N_NODES * HID];    // x @ W1
__device__ float g_h2[N_NODES * HID];    // z @ W2
__device__ float g_agg1[N_NODES * HID];  // layer-1 scatter target
__device__ float g_deg[N_NODES];
__device__ float g_dinv[N_NODES];

// ---------------- init: zero agg buffers, deg = 1 (self-loop) -------------------
__global__ void init_kernel(float* __restrict__ out) {
    int t = blockIdx.x * blockDim.x + threadIdx.x;
    if (t < N_NODES * HID / 4) {
        ((float4*)g_agg1)[t] = make_float4(0.f, 0.f, 0.f, 0.f);
        ((float4*)out)[t]    = make_float4(0.f, 0.f, 0.f, 0.f);
    }
    if (t < N_NODES) g_deg[t] = 1.0f;
}

// ---------------- degree: count incoming edges ----------------------------------
__global__ void deg_kernel(const int* __restrict__ dst) {
    int e = blockIdx.x * blockDim.x + threadIdx.x;
    if (e < N_EDGES) atomicAdd(&g_deg[dst[e]], 1.0f);
}

__global__ void dinv_kernel() {
    int i = blockIdx.x * blockDim.x + threadIdx.x;
    if (i < N_NODES) g_dinv[i] = rsqrtf(g_deg[i]);
}

// ---------------- GEMM1: h1 = x @ W1   (100000x512 @ 512x32, fp32) --------------
// 128 rows/block, one row per thread, packed f32x2 FMA (16 accumulator pairs).
__global__ void __launch_bounds__(128) gemm1_kernel(const float* __restrict__ x,
                                                    const float* __restrict__ W1) {
    __shared__ float xs[128 * 65];   // padded stride 65 -> conflict-free column reads
    __shared__ float ws[64 * HID];   // 64-k chunk of W1

    const int tid = threadIdx.x;
    const int rowBase = blockIdx.x * 128;

    unsigned long long acc[16];
#pragma unroll
    for (int j = 0; j < 16; j++) acc[j] = 0ULL;

    for (int kc = 0; kc < IN_DIM; kc += 64) {
        // load x tile: 128 rows x 64 cols (coalesced float4, scalar STS with pad)
#pragma unroll
        for (int i = 0; i < 16; i++) {
            int idx = tid + i * 128;        // 0..2047
            int r   = idx >> 4;             // row within tile
            int c4  = idx & 15;             // float4 column
            int grow = rowBase + r;
            if (grow >= N_NODES) grow = N_NODES - 1;  // clamp tail (harmless dup)
            float4 v = ((const float4*)x)[(size_t)grow * (IN_DIM / 4) + (kc >> 2) + c4];
            float* p = &xs[r * 65 + c4 * 4];
            p[0] = v.x; p[1] = v.y; p[2] = v.z; p[3] = v.w;
        }
        // load W1 chunk: 64x32 floats
#pragma unroll
        for (int i = 0; i < 4; i++)
            ((float4*)ws)[tid + i * 128] = ((const float4*)(W1 + kc * HID))[tid + i * 128];
        __syncthreads();

#pragma unroll 4
        for (int k = 0; k < 64; k++) {
            unsigned int xu = __float_as_uint(xs[tid * 65 + k]);
            unsigned long long xp;
            asm("mov.b64 %0, {%1, %1};" : "=l"(xp) : "r"(xu));
            const unsigned long long* wrow = (const unsigned long long*)&ws[k * HID];
#pragma unroll
            for (int j = 0; j < 16; j++)
                asm("fma.rn.f32x2 %0, %1, %2, %0;" : "+l"(acc[j]) : "l"(xp), "l"(wrow[j]));
        }
        __syncthreads();
    }

    int row = rowBase + tid;
    if (row < N_NODES) {
        float2* o = (float2*)&g_h1[(size_t)row * HID];
#pragma unroll
        for (int j = 0; j < 16; j++) {
            float2 v;
            v.x = __uint_as_float((unsigned)(acc[j] & 0xffffffffULL));
            v.y = __uint_as_float((unsigned)(acc[j] >> 32));
            o[j] = v;
        }
    }
}

// ---------------- scatter: agg[dst] += h[src] * dinv[src]*dinv[dst] -------------
// 8 threads per edge, float4 gather + red.global.add.v2 (h & agg are L2-resident).
__device__ __forceinline__ void scatter_body(int t, const int* __restrict__ src,
                                             const int* __restrict__ dst,
                                             const float* __restrict__ h,
                                             float* __restrict__ agg) {
    int e = t >> 3;
    if (e >= N_EDGES) return;
    int c = (t & 7) << 2;
    int s = src[e], d = dst[e];
    float coef = g_dinv[s] * g_dinv[d];
    float4 v = *(const float4*)&h[(size_t)s * HID + c];
    float* ap = agg + (size_t)d * HID + c;
    asm volatile("red.global.add.v2.f32 [%0], {%1, %2};"
                 :: "l"(ap), "f"(v.x * coef), "f"(v.y * coef) : "memory");
    asm volatile("red.global.add.v2.f32 [%0], {%1, %2};"
                 :: "l"(ap + 2), "f"(v.z * coef), "f"(v.w * coef) : "memory");
}

__global__ void scatter1_kernel(const int* __restrict__ src, const int* __restrict__ dst) {
    int t = blockIdx.x * blockDim.x + threadIdx.x;
    scatter_body(t, src, dst, g_h1, g_agg1);
}

__global__ void scatter2_kernel(const int* __restrict__ src, const int* __restrict__ dst,
                                float* __restrict__ out) {
    int t = blockIdx.x * blockDim.x + threadIdx.x;
    scatter_body(t, src, dst, g_h2, out);
}

// ---------------- layer2: z = BN(relu(agg1 + h1*dinv^2 + b1)); h2 = z @ W2 ------
__global__ void __launch_bounds__(128) layer2_kernel(const float* __restrict__ b1,
                                                     const float* __restrict__ W2,
                                                     const float* __restrict__ gamma,
                                                     const float* __restrict__ beta,
                                                     const float* __restrict__ rmean,
                                                     const float* __restrict__ rvar) {
    __shared__ float ws[HID * HID];
    __shared__ float sb1[HID], sscale[HID], sshift[HID];
    int tid = threadIdx.x;
    for (int i = tid; i < HID * HID / 4; i += 128)
        ((float4*)ws)[i] = ((const float4*)W2)[i];
    if (tid < HID) {
        float sc = gamma[tid] * rsqrtf(rvar[tid] + BN_EPS);
        sscale[tid] = sc;
        sshift[tid] = beta[tid] - rmean[tid] * sc;
        sb1[tid]    = b1[tid];
    }
    __syncthreads();

    int node = blockIdx.x * 128 + tid;
    if (node >= N_NODES) return;

    float di = g_dinv[node];
    float d2 = di * di;

    float z[HID];
    const float4* a4 = (const float4*)&g_agg1[(size_t)node * HID];
    const float4* h4 = (const float4*)&g_h1[(size_t)node * HID];
#pragma unroll
    for (int i = 0; i < 8; i++) {
        float4 a = a4[i], h = h4[i];
        int k = i * 4;
        float v;
        v = a.x + h.x * d2 + sb1[k + 0]; v = fmaxf(v, 0.f); z[k + 0] = v * sscale[k + 0] + sshift[k + 0];
        v = a.y + h.y * d2 + sb1[k + 1]; v = fmaxf(v, 0.f); z[k + 1] = v * sscale[k + 1] + sshift[k + 1];
        v = a.z + h.z * d2 + sb1[k + 2]; v = fmaxf(v, 0.f); z[k + 2] = v * sscale[k + 2] + sshift[k + 2];
        v = a.w + h.w * d2 + sb1[k + 3]; v = fmaxf(v, 0.f); z[k + 3] = v * sscale[k + 3] + sshift[k + 3];
    }

    unsigned long long acc[16];
#pragma unroll
    for (int j = 0; j < 16; j++) acc[j] = 0ULL;
#pragma unroll
    for (int k = 0; k < HID; k++) {
        unsigned int zu = __float_as_uint(z[k]);
        unsigned long long zp;
        asm("mov.b64 %0, {%1, %1};" : "=l"(zp) : "r"(zu));
        const unsigned long long* wrow = (const unsigned long long*)&ws[k * HID];
#pragma unroll
        for (int j = 0; j < 16; j++)
            asm("fma.rn.f32x2 %0, %1, %2, %0;" : "+l"(acc[j]) : "l"(zp), "l"(wrow[j]));
    }

    float2* o = (float2*)&g_h2[(size_t)node * HID];
#pragma unroll
    for (int j = 0; j < 16; j++) {
        float2 v;
        v.x = __uint_as_float((unsigned)(acc[j] & 0xffffffffULL));
        v.y = __uint_as_float((unsigned)(acc[j] >> 32));
        o[j] = v;
    }
}

// ---------------- finalize: out = relu(agg2 + h2*dinv^2 + b2) -------------------
__global__ void final_kernel(float* __restrict__ out, const float* __restrict__ b2) {
    int t = blockIdx.x * blockDim.x + threadIdx.x;
    if (t >= N_NODES * 8) return;
    int node = t >> 3;
    int c = (t & 7) << 2;
    float di = g_dinv[node];
    float d2 = di * di;
    float4 a = *(float4*)(out + (size_t)node * HID + c);
    float4 h = *(const float4*)&g_h2[(size_t)node * HID + c];
    float4 b = *(const float4*)(b2 + c);
    float4 r;
    r.x = fmaxf(a.x + h.x * d2 + b.x, 0.f);
    r.y = fmaxf(a.y + h.y * d2 + b.y, 0.f);
    r.z = fmaxf(a.z + h.z * d2 + b.z, 0.f);
    r.w = fmaxf(a.w + h.w * d2 + b.w, 0.f);
    *(float4*)(out + (size_t)node * HID + c) = r;
}

// ---------------- launch ---------------------------------------------------------
extern "C" void kernel_launch(void* const* d_in, const int* in_sizes, int n_in,
                              void* d_out, int out_size) {
    const float* x     = (const float*)d_in[0];
    const int*   ei    = (const int*)  d_in[1];
    const float* W1    = (const float*)d_in[2];
    const float* b1    = (const float*)d_in[3];
    const float* W2    = (const float*)d_in[4];
    const float* b2    = (const float*)d_in[5];
    const float* gamma = (const float*)d_in[6];
    const float* beta  = (const float*)d_in[7];
    const float* rmean = (const float*)d_in[8];
    const float* rvar  = (const float*)d_in[9];
    float* out = (float*)d_out;

    const int* src = ei;
    const int* dst = ei + N_EDGES;

    init_kernel<<<(N_NODES * HID / 4 + 255) / 256, 256>>>(out);
    deg_kernel<<<(N_EDGES + 255) / 256, 256>>>(dst);
    dinv_kernel<<<(N_NODES + 255) / 256, 256>>>();
    gemm1_kernel<<<(N_NODES + 127) / 128, 128>>>(x, W1);
    scatter1_kernel<<<(N_EDGES * 8 + 255) / 256, 256>>>(src, dst);
    layer2_kernel<<<(N_NODES + 127) / 128, 128>>>(b1, W2, gamma, beta, rmean, rvar);
    scatter2_kernel<<<(N_EDGES * 8 + 255) / 256, 256>>>(src, dst, out);
    final_kernel<<<(N_NODES * 8 + 255) / 256, 256>>>(out, b2);
}

// round 11
// speedup vs baseline: 1.2588x; 1.2588x over previous
#include <cuda_runtime.h>

#define N_NODES 100000
#define N_EDGES 1600000
#define IN_DIM  512
#define HID     32
#define BN_EPS  1e-5f

// ---------------- scratch (static device globals; no allocation) ----------------
__device__ float g_h1[N_NODES * HID];    // x @ W1
__device__ float g_h2[N_NODES * HID];    // z @ W2
__device__ float g_agg1[N_NODES * HID];  // layer-1 scatter target
__device__ float g_deg[N_NODES];
__device__ float g_dinv[N_NODES];

// ---------------- init: zero agg buffers, deg = 1 (self-loop) -------------------
__global__ void init_kernel(float* __restrict__ out) {
    int t = blockIdx.x * blockDim.x + threadIdx.x;
    if (t < N_NODES * HID / 4) {
        ((float4*)g_agg1)[t] = make_float4(0.f, 0.f, 0.f, 0.f);
        ((float4*)out)[t]    = make_float4(0.f, 0.f, 0.f, 0.f);
    }
    if (t < N_NODES) g_deg[t] = 1.0f;
}

// ---------------- degree: count incoming edges ----------------------------------
__global__ void deg_kernel(const int* __restrict__ dst) {
    int e = blockIdx.x * blockDim.x + threadIdx.x;
    if (e < N_EDGES) atomicAdd(&g_deg[dst[e]], 1.0f);
}

__global__ void dinv_kernel() {
    int i = blockIdx.x * blockDim.x + threadIdx.x;
    if (i < N_NODES) g_dinv[i] = rsqrtf(g_deg[i]);
}

// ---------------- GEMM1: h1 = x @ W1   (100000x512 @ 512x32, fp32) --------------
// 64 threads/block, 2 rows/thread (128 rows/block), TILE_K=32.
// W chunk read once per k as LDS.128 (ulonglong2) and reused for BOTH rows ->
// LSU:FMA ratio ~0.6, FMA2-pipe bound. x tile padded to stride 36 so per-row
// reads are conflict-free LDS.128.
#define G1_THREADS 64
#define G1_ROWS    128
#define G1_TILE_K  32
#define G1_XSTRIDE 36   // floats; mult of 4 (16B aligned), (4*tid+k)&31 distinct per phase

__device__ __forceinline__ unsigned long long dup_f32(float v) {
    unsigned long long p;
    asm("mov.b64 %0, {%1, %1};" : "=l"(p) : "r"(__float_as_uint(v)));
    return p;
}

__global__ void __launch_bounds__(G1_THREADS) gemm1_kernel(const float* __restrict__ x,
                                                           const float* __restrict__ W1) {
    __shared__ __align__(16) float xs[G1_ROWS * G1_XSTRIDE];  // 18.4 KB
    __shared__ __align__(16) float ws[G1_TILE_K * HID];       // 4 KB

    const int tid = threadIdx.x;
    const int rowBase = blockIdx.x * G1_ROWS;

    unsigned long long accA[16], accB[16];
#pragma unroll
    for (int j = 0; j < 16; j++) { accA[j] = 0ULL; accB[j] = 0ULL; }

    for (int kc = 0; kc < IN_DIM; kc += G1_TILE_K) {
        // stage x tile: 128 rows x 32 cols = 1024 float4, 16 per thread (coalesced)
#pragma unroll
        for (int i = 0; i < 16; i++) {
            int idx = tid + i * G1_THREADS;   // 0..1023
            int r   = idx >> 3;               // row in tile
            int c4  = idx & 7;                // float4 col
            int grow = rowBase + r;
            if (grow >= N_NODES) grow = N_NODES - 1;   // clamp tail (dup, write-guarded)
            float4 v = ((const float4*)x)[(size_t)grow * (IN_DIM / 4) + (kc >> 2) + c4];
            *(float4*)&xs[r * G1_XSTRIDE + c4 * 4] = v;
        }
        // stage W chunk: 32x32 floats = 256 float4, 4 per thread
#pragma unroll
        for (int i = 0; i < 4; i++)
            ((float4*)ws)[tid + i * G1_THREADS] =
                ((const float4*)(W1 + kc * HID))[tid + i * G1_THREADS];
        __syncthreads();

        const int r0 = tid;
        const int r1 = tid + G1_THREADS;
#pragma unroll
        for (int k4 = 0; k4 < G1_TILE_K / 4; k4++) {
            float4 xa = *(const float4*)&xs[r0 * G1_XSTRIDE + k4 * 4];
            float4 xb = *(const float4*)&xs[r1 * G1_XSTRIDE + k4 * 4];
            float xav[4] = {xa.x, xa.y, xa.z, xa.w};
            float xbv[4] = {xb.x, xb.y, xb.z, xb.w};
#pragma unroll
            for (int kk = 0; kk < 4; kk++) {
                int k = k4 * 4 + kk;
                unsigned long long xpa = dup_f32(xav[kk]);
                unsigned long long xpb = dup_f32(xbv[kk]);
                const ulonglong2* w4 = (const ulonglong2*)&ws[k * HID];
#pragma unroll
                for (int j = 0; j < 8; j++) {
                    ulonglong2 w = w4[j];   // LDS.128 broadcast, reused 4x
                    asm("fma.rn.f32x2 %0, %1, %2, %0;" : "+l"(accA[2*j])   : "l"(xpa), "l"(w.x));
                    asm("fma.rn.f32x2 %0, %1, %2, %0;" : "+l"(accA[2*j+1]) : "l"(xpa), "l"(w.y));
                    asm("fma.rn.f32x2 %0, %1, %2, %0;" : "+l"(accB[2*j])   : "l"(xpb), "l"(w.x));
                    asm("fma.rn.f32x2 %0, %1, %2, %0;" : "+l"(accB[2*j+1]) : "l"(xpb), "l"(w.y));
                }
            }
        }
        __syncthreads();
    }

    int rowA = rowBase + tid;
    int rowB = rowBase + tid + G1_THREADS;
    if (rowA < N_NODES) {
        float2* o = (float2*)&g_h1[(size_t)rowA * HID];
#pragma unroll
        for (int j = 0; j < 16; j++) {
            float2 v;
            v.x = __uint_as_float((unsigned)(accA[j] & 0xffffffffULL));
            v.y = __uint_as_float((unsigned)(accA[j] >> 32));
            o[j] = v;
        }
    }
    if (rowB < N_NODES) {
        float2* o = (float2*)&g_h1[(size_t)rowB * HID];
#pragma unroll
        for (int j = 0; j < 16; j++) {
            float2 v;
            v.x = __uint_as_float((unsigned)(accB[j] & 0xffffffffULL));
            v.y = __uint_as_float((unsigned)(accB[j] >> 32));
            o[j] = v;
        }
    }
}

// ---------------- scatter: agg[dst] += h[src] * dinv[src]*dinv[dst] -------------
// 8 threads per edge, float4 gather + red.global.add.v2 (h & agg are L2-resident).
__device__ __forceinline__ void scatter_body(int t, const int* __restrict__ src,
                                             const int* __restrict__ dst,
                                             const float* __restrict__ h,
                                             float* __restrict__ agg) {
    int e = t >> 3;
    if (e >= N_EDGES) return;
    int c = (t & 7) << 2;
    int s = src[e], d = dst[e];
    float coef = g_dinv[s] * g_dinv[d];
    float4 v = *(const float4*)&h[(size_t)s * HID + c];
    float* ap = agg + (size_t)d * HID + c;
    asm volatile("red.global.add.v2.f32 [%0], {%1, %2};"
                 :: "l"(ap), "f"(v.x * coef), "f"(v.y * coef) : "memory");
    asm volatile("red.global.add.v2.f32 [%0], {%1, %2};"
                 :: "l"(ap + 2), "f"(v.z * coef), "f"(v.w * coef) : "memory");
}

__global__ void scatter1_kernel(const int* __restrict__ src, const int* __restrict__ dst) {
    int t = blockIdx.x * blockDim.x + threadIdx.x;
    scatter_body(t, src, dst, g_h1, g_agg1);
}

__global__ void scatter2_kernel(const int* __restrict__ src, const int* __restrict__ dst,
                                float* __restrict__ out) {
    int t = blockIdx.x * blockDim.x + threadIdx.x;
    scatter_body(t, src, dst, g_h2, out);
}

// ---------------- layer2: z = BN(relu(agg1 + h1*dinv^2 + b1)); h2 = z @ W2 ------
__global__ void __launch_bounds__(128) layer2_kernel(const float* __restrict__ b1,
                                                     const float* __restrict__ W2,
                                                     const float* __restrict__ gamma,
                                                     const float* __restrict__ beta,
                                                     const float* __restrict__ rmean,
                                                     const float* __restrict__ rvar) {
    __shared__ float ws[HID * HID];
    __shared__ float sb1[HID], sscale[HID], sshift[HID];
    int tid = threadIdx.x;
    for (int i = tid; i < HID * HID / 4; i += 128)
        ((float4*)ws)[i] = ((const float4*)W2)[i];
    if (tid < HID) {
        float sc = gamma[tid] * rsqrtf(rvar[tid] + BN_EPS);
        sscale[tid] = sc;
        sshift[tid] = beta[tid] - rmean[tid] * sc;
        sb1[tid]    = b1[tid];
    }
    __syncthreads();

    int node = blockIdx.x * 128 + tid;
    if (node >= N_NODES) return;

    float di = g_dinv[node];
    float d2 = di * di;

    float z[HID];
    const float4* a4 = (const float4*)&g_agg1[(size_t)node * HID];
    const float4* h4 = (const float4*)&g_h1[(size_t)node * HID];
#pragma unroll
    for (int i = 0; i < 8; i++) {
        float4 a = a4[i], h = h4[i];
        int k = i * 4;
        float v;
        v = a.x + h.x * d2 + sb1[k + 0]; v = fmaxf(v, 0.f); z[k + 0] = v * sscale[k + 0] + sshift[k + 0];
        v = a.y + h.y * d2 + sb1[k + 1]; v = fmaxf(v, 0.f); z[k + 1] = v * sscale[k + 1] + sshift[k + 1];
        v = a.z + h.z * d2 + sb1[k + 2]; v = fmaxf(v, 0.f); z[k + 2] = v * sscale[k + 2] + sshift[k + 2];
        v = a.w + h.w * d2 + sb1[k + 3]; v = fmaxf(v, 0.f); z[k + 3] = v * sscale[k + 3] + sshift[k + 3];
    }

    unsigned long long acc[16];
#pragma unroll
    for (int j = 0; j < 16; j++) acc[j] = 0ULL;
#pragma unroll
    for (int k = 0; k < HID; k++) {
        unsigned long long zp = dup_f32(z[k]);
        const ulonglong2* w4 = (const ulonglong2*)&ws[k * HID];
#pragma unroll
        for (int j = 0; j < 8; j++) {
            ulonglong2 w = w4[j];
            asm("fma.rn.f32x2 %0, %1, %2, %0;" : "+l"(acc[2*j])   : "l"(zp), "l"(w.x));
            asm("fma.rn.f32x2 %0, %1, %2, %0;" : "+l"(acc[2*j+1]) : "l"(zp), "l"(w.y));
        }
    }

    float2* o = (float2*)&g_h2[(size_t)node * HID];
#pragma unroll
    for (int j = 0; j < 16; j++) {
        float2 v;
        v.x = __uint_as_float((unsigned)(acc[j] & 0xffffffffULL));
        v.y = __uint_as_float((unsigned)(acc[j] >> 32));
        o[j] = v;
    }
}

// ---------------- finalize: out = relu(agg2 + h2*dinv^2 + b2) -------------------
__global__ void final_kernel(float* __restrict__ out, const float* __restrict__ b2) {
    int t = blockIdx.x * blockDim.x + threadIdx.x;
    if (t >= N_NODES * 8) return;
    int node = t >> 3;
    int c = (t & 7) << 2;
    float di = g_dinv[node];
    float d2 = di * di;
    float4 a = *(float4*)(out + (size_t)node * HID + c);
    float4 h = *(const float4*)&g_h2[(size_t)node * HID + c];
    float4 b = *(const float4*)(b2 + c);
    float4 r;
    r.x = fmaxf(a.x + h.x * d2 + b.x, 0.f);
    r.y = fmaxf(a.y + h.y * d2 + b.y, 0.f);
    r.z = fmaxf(a.z + h.z * d2 + b.z, 0.f);
    r.w = fmaxf(a.w + h.w * d2 + b.w, 0.f);
    *(float4*)(out + (size_t)node * HID + c) = r;
}

// ---------------- launch ---------------------------------------------------------
extern "C" void kernel_launch(void* const* d_in, const int* in_sizes, int n_in,
                              void* d_out, int out_size) {
    const float* x     = (const float*)d_in[0];
    const int*   ei    = (const int*)  d_in[1];
    const float* W1    = (const float*)d_in[2];
    const float* b1    = (const float*)d_in[3];
    const float* W2    = (const float*)d_in[4];
    const float* b2    = (const float*)d_in[5];
    const float* gamma = (const float*)d_in[6];
    const float* beta  = (const float*)d_in[7];
    const float* rmean = (const float*)d_in[8];
    const float* rvar  = (const float*)d_in[9];
    float* out = (float*)d_out;

    const int* src = ei;
    const int* dst = ei + N_EDGES;

    init_kernel<<<(N_NODES * HID / 4 + 255) / 256, 256>>>(out);
    deg_kernel<<<(N_EDGES + 255) / 256, 256>>>(dst);
    dinv_kernel<<<(N_NODES + 255) / 256, 256>>>();
    gemm1_kernel<<<(N_NODES + G1_ROWS - 1) / G1_ROWS, G1_THREADS>>>(x, W1);
    scatter1_kernel<<<(N_EDGES * 8 + 255) / 256, 256>>>(src, dst);
    layer2_kernel<<<(N_NODES + 127) / 128, 128>>>(b1, W2, gamma, beta, rmean, rvar);
    scatter2_kernel<<<(N_EDGES * 8 + 255) / 256, 256>>>(src, dst, out);
    final_kernel<<<(N_NODES * 8 + 255) / 256, 256>>>(out, b2);
}